// round 3
// baseline (speedup 1.0000x reference)
#include <cuda_runtime.h>

#define BATCH 2
#define C     48
#define C3    144
#define DD    32
#define HD    64
#define WD    64
#define LL    (DD*HD*WD)   /* 131072 */
#define HW    (HD*WD)      /* 4096 */
#define HEADS 6
#define CPH   8

typedef unsigned long long ull;

// ---- packed f32x2 helpers (Blackwell) ----
__device__ __forceinline__ ull pack2(float a, float b) {
    ull r; asm("mov.b64 %0, {%1,%2};" : "=l"(r) : "f"(a), "f"(b)); return r;
}
__device__ __forceinline__ float2 unpack2(ull v) {
    float2 r; asm("mov.b64 {%0,%1}, %2;" : "=f"(r.x), "=f"(r.y) : "l"(v)); return r;
}
__device__ __forceinline__ void fma2(ull& d, ull a, ull b) {
    asm("fma.rn.f32x2 %0, %1, %2, %0;" : "+l"(d) : "l"(a), "l"(b));
}

// ---- scratch (static device arrays; no runtime allocation) ----
__device__ float g_qkv[(size_t)BATCH * C3 * LL];   // after 1x1x1 conv
__device__ float g_dw [(size_t)BATCH * C3 * LL];   // after depthwise conv
__device__ float g_attn[BATCH * HEADS * CPH * CPH];
__device__ float g_weff[BATCH * C * C];

// ---------------------------------------------------------------------------
// K0: zero the attention accumulator
// ---------------------------------------------------------------------------
__global__ void k0_zero() {
    g_attn[threadIdx.x] = 0.0f;
}

// ---------------------------------------------------------------------------
// K1: qkv = W1[144x48] * x[48xL] + b1    (per batch)
// 288 threads; W loaded once; 4 phases of 64 l. Inner loop uses fma.rn.f32x2
// packed over the oc dimension (weight pairs read directly via LDS.64).
// ---------------------------------------------------------------------------
__global__ __launch_bounds__(288) void k1_qkv(const float* __restrict__ x,
                                              const float* __restrict__ w1,
                                              const float* __restrict__ b1) {
    __shared__ float  Wt[48][144];   // [ic][oc]
    __shared__ float4 Xs[48][16];    // [ic][l/4]

    const int b  = blockIdx.y;
    const size_t l0 = (size_t)blockIdx.x * 256;
    const int tid = threadIdx.x;

    for (int i = tid; i < C3 * C; i += 288) {
        int oc = i / 48, ic = i % 48;
        Wt[ic][oc] = w1[i];
    }

    const int lq  = tid & 15;        // 0..15 -> one float4 (4 l's)
    const int og  = tid >> 4;        // 0..17 -> 8 oc's each
    const int oc0 = og * 8;

    ull bp[4];
#pragma unroll
    for (int p = 0; p < 4; p++) bp[p] = pack2(b1[oc0 + 2*p], b1[oc0 + 2*p + 1]);

#pragma unroll 1
    for (int phase = 0; phase < 4; phase++) {
        const size_t lp = l0 + phase * 64;
        __syncthreads();
        for (int i = tid; i < 48 * 16; i += 288) {
            int ic = i >> 4, j = i & 15;
            Xs[ic][j] = *(const float4*)(x + ((size_t)b * C + ic) * LL + lp + j * 4);
        }
        __syncthreads();

        ull acc[4][4];   // [oc-pair][l]
#pragma unroll
        for (int p = 0; p < 4; p++)
#pragma unroll
            for (int li = 0; li < 4; li++) acc[p][li] = bp[p];

#pragma unroll 4
        for (int ic = 0; ic < 48; ic++) {
            const float4 xv = Xs[ic][lq];
            ull xl[4];
            xl[0] = pack2(xv.x, xv.x);
            xl[1] = pack2(xv.y, xv.y);
            xl[2] = pack2(xv.z, xv.z);
            xl[3] = pack2(xv.w, xv.w);
            const ull* wrow = (const ull*)&Wt[ic][oc0];   // 4 oc-pairs
#pragma unroll
            for (int p = 0; p < 4; p++) {
                const ull wp = wrow[p];
#pragma unroll
                for (int li = 0; li < 4; li++) fma2(acc[p][li], wp, xl[li]);
            }
        }

#pragma unroll
        for (int p = 0; p < 4; p++) {
            float2 u0 = unpack2(acc[p][0]);
            float2 u1 = unpack2(acc[p][1]);
            float2 u2 = unpack2(acc[p][2]);
            float2 u3 = unpack2(acc[p][3]);
            float4 lo = make_float4(u0.x, u1.x, u2.x, u3.x);
            float4 hi = make_float4(u0.y, u1.y, u2.y, u3.y);
            *(float4*)&g_qkv[((size_t)b * C3 + oc0 + 2*p    ) * LL + lp + lq * 4] = lo;
            *(float4*)&g_qkv[((size_t)b * C3 + oc0 + 2*p + 1) * LL + lp + lq * 4] = hi;
        }
    }
}

// ---------------------------------------------------------------------------
// K2: depthwise 3x3x3 SAME conv, 144 channels. One warp per (b, ch, h).
// Rolling d-window; all pairs pre-packed at row-load time; d-loop body is
// 27 fma.rn.f32x2.
// ---------------------------------------------------------------------------
__global__ __launch_bounds__(256, 2) void k2_dw(const float* __restrict__ wdw,
                                                const float* __restrict__ bdw) {
    const int gw   = blockIdx.x * 8 + (threadIdx.x >> 5);
    const int lane = threadIdx.x & 31;
    const int h  = gw % HD;
    const int t  = gw / HD;
    const int ch = t % C3;
    const int b  = t / C3;

    const float* base  = g_qkv + ((size_t)b * C3 + ch) * LL;
    float*       obase = g_dw  + ((size_t)b * C3 + ch) * LL;

    ull wp[27];
#pragma unroll
    for (int i = 0; i < 27; i++) { float w = wdw[ch * 27 + i]; wp[i] = pack2(w, w); }
    const float bias = bdw[ch];
    const ull biasp = pack2(bias, bias);

    // packed row triples: A={w-1,w0}, B={w0,w1}, C={w1,w+2}
    ull pA[3][3], pB[3][3], pC[3][3];

    auto loadrow = [&](int d, int hh, int s) {
        const int hr = h + hh - 1;
        float2 v2;
        if (d < 0 || d >= DD || hr < 0 || hr >= HD) v2 = make_float2(0.f, 0.f);
        else v2 = ((const float2*)(base + (size_t)d * HW + hr * WD))[lane];
        float a = __shfl_up_sync(0xffffffffu, v2.y, 1);
        if (lane == 0) a = 0.f;
        float p = __shfl_down_sync(0xffffffffu, v2.x, 1);
        if (lane == 31) p = 0.f;
        pA[s][hh] = pack2(a, v2.x);
        pB[s][hh] = pack2(v2.x, v2.y);
        pC[s][hh] = pack2(v2.y, p);
    };

#pragma unroll
    for (int hh = 0; hh < 3; hh++) {
        pA[0][hh] = 0ULL; pB[0][hh] = 0ULL; pC[0][hh] = 0ULL;
        loadrow(0, hh, 1);
        loadrow(1, hh, 2);
    }

    for (int d = 0; d < DD; d++) {
        ull o = biasp;
#pragma unroll
        for (int dd = 0; dd < 3; dd++) {
#pragma unroll
            for (int hh = 0; hh < 3; hh++) {
                const int tb = (dd * 3 + hh) * 3;
                fma2(o, wp[tb    ], pA[dd][hh]);
                fma2(o, wp[tb + 1], pB[dd][hh]);
                fma2(o, wp[tb + 2], pC[dd][hh]);
            }
        }
        float2 ov = unpack2(o);
        ((float2*)(obase + (size_t)d * HW + h * WD))[lane] = ov;
#pragma unroll
        for (int hh = 0; hh < 3; hh++) {
            pA[0][hh] = pA[1][hh]; pB[0][hh] = pB[1][hh]; pC[0][hh] = pC[1][hh];
            pA[1][hh] = pA[2][hh]; pB[1][hh] = pB[2][hh]; pC[1][hh] = pC[2][hh];
            loadrow(d + 2, hh, 2);
        }
    }
}

// ---------------------------------------------------------------------------
// K3: attn[b,h,c,d] += sum_l q[b,h,c,l] * k[b,h,d,l]
// grid = (L/4096, B*HEADS) = 384 blocks (2 CTAs/SM); float2 loads, 8 iters
// ---------------------------------------------------------------------------
__global__ __launch_bounds__(256) void k3_attn() {
    const int chunk = blockIdx.x;
    const int bh = blockIdx.y;
    const int b = bh / HEADS, hd = bh % HEADS;

    const float* qb = g_dw + ((size_t)b * C3 + hd * CPH) * LL + (size_t)chunk * 4096;
    const float* kb = qb + (size_t)C * LL;

    float acc[64];
#pragma unroll
    for (int i = 0; i < 64; i++) acc[i] = 0.f;

#pragma unroll 1
    for (int it = 0; it < 8; it++) {
        const int l2 = it * 256 + threadIdx.x;   // float2 index within chunk
        float2 q[8], k[8];
#pragma unroll
        for (int i = 0; i < 8; i++) {
            q[i] = ((const float2*)(qb + (size_t)i * LL))[l2];
            k[i] = ((const float2*)(kb + (size_t)i * LL))[l2];
        }
#pragma unroll
        for (int i = 0; i < 8; i++)
#pragma unroll
            for (int j = 0; j < 8; j++)
                acc[i * 8 + j] += q[i].x * k[j].x + q[i].y * k[j].y;
    }

    __shared__ float red[64];
    if (threadIdx.x < 64) red[threadIdx.x] = 0.f;
    __syncthreads();
    const int lane = threadIdx.x & 31;
#pragma unroll
    for (int v = 0; v < 64; v++) {
        float s = acc[v];
#pragma unroll
        for (int off = 16; off > 0; off >>= 1)
            s += __shfl_xor_sync(0xffffffffu, s, off);
        if (lane == 0) atomicAdd(&red[v], s);
    }
    __syncthreads();
    if (threadIdx.x < 64)
        atomicAdd(&g_attn[bh * 64 + threadIdx.x], red[threadIdx.x]);
}

// ---------------------------------------------------------------------------
// K4: softmax(scale*attn + mask) then fold proj into a per-batch 48x48 Weff
// ---------------------------------------------------------------------------
__global__ __launch_bounds__(256) void k4_soft(const float* __restrict__ mask,
                                               const float* __restrict__ wproj) {
    const int tid = threadIdx.x;
    __shared__ float A[BATCH * HEADS * CPH * CPH];
    const float scale = 0.40824829046386307f;  // 6^-0.5

    if (tid < BATCH * HEADS * CPH) {  // 96 rows
        const int b = tid / (HEADS * CPH);
        const int r = tid % (HEADS * CPH);
        const int hd = r / CPH, c = r % CPH;
        float v[8];
        float mx = -1e30f;
#pragma unroll
        for (int j = 0; j < 8; j++) {
            v[j] = g_attn[((b * HEADS + hd) * CPH + c) * CPH + j] * scale
                 + mask[(b * CPH + c) * CPH + j];
            mx = fmaxf(mx, v[j]);
        }
        float s = 0.f;
#pragma unroll
        for (int j = 0; j < 8; j++) { v[j] = expf(v[j] - mx); s += v[j]; }
        const float inv = 1.f / s;
#pragma unroll
        for (int j = 0; j < 8; j++)
            A[((b * HEADS + hd) * CPH + c) * CPH + j] = v[j] * inv;
    }
    __syncthreads();

    for (int i = tid; i < BATCH * C * C; i += 256) {
        const int b = i / (C * C);
        const int r = i % (C * C);
        const int oc = r / C, c2 = r % C;
        const int hd = c2 / CPH, j = c2 % CPH;
        float s = 0.f;
#pragma unroll
        for (int ii = 0; ii < 8; ii++)
            s += wproj[oc * C + hd * CPH + ii]
               * A[((b * HEADS + hd) * CPH + ii) * CPH + j];
        g_weff[i] = s;
    }
}

// ---------------------------------------------------------------------------
// K5: out[48,L] = Weff[b][48x48] * v_dw[48,L] + b_proj   (fma.f32x2 inner)
// 192 threads; W loaded once; 2 phases of 128 l
// ---------------------------------------------------------------------------
__global__ __launch_bounds__(192) void k5_proj(const float* __restrict__ bproj,
                                               float* __restrict__ outp) {
    __shared__ float  Wt[48][48];    // [c2][oc]
    __shared__ float4 Vs[48][32];    // [c2][l/4]

    const int b  = blockIdx.y;
    const size_t l0 = (size_t)blockIdx.x * 256;
    const int tid = threadIdx.x;

    for (int i = tid; i < C * C; i += 192) {
        int oc = i / 48, c2 = i % 48;
        Wt[c2][oc] = g_weff[b * C * C + i];
    }

    const int lq  = tid & 31;   // one float4 (4 l's)
    const int og  = tid >> 5;   // 0..5 -> 8 oc's each
    const int oc0 = og * 8;

    ull bp[4];
#pragma unroll
    for (int p = 0; p < 4; p++) bp[p] = pack2(bproj[oc0 + 2*p], bproj[oc0 + 2*p + 1]);

#pragma unroll 1
    for (int phase = 0; phase < 2; phase++) {
        const size_t lp = l0 + phase * 128;
        __syncthreads();
        for (int i = tid; i < 48 * 32; i += 192) {
            int ic = i >> 5, j = i & 31;
            Vs[ic][j] = *(const float4*)(g_dw + ((size_t)b * C3 + 2 * C + ic) * LL + lp + j * 4);
        }
        __syncthreads();

        ull acc[4][4];
#pragma unroll
        for (int p = 0; p < 4; p++)
#pragma unroll
            for (int li = 0; li < 4; li++) acc[p][li] = bp[p];

#pragma unroll 4
        for (int c2 = 0; c2 < 48; c2++) {
            const float4 xv = Vs[c2][lq];
            ull xl[4];
            xl[0] = pack2(xv.x, xv.x);
            xl[1] = pack2(xv.y, xv.y);
            xl[2] = pack2(xv.z, xv.z);
            xl[3] = pack2(xv.w, xv.w);
            const ull* wrow = (const ull*)&Wt[c2][oc0];
#pragma unroll
            for (int p = 0; p < 4; p++) {
                const ull wpv = wrow[p];
#pragma unroll
                for (int li = 0; li < 4; li++) fma2(acc[p][li], wpv, xl[li]);
            }
        }

#pragma unroll
        for (int p = 0; p < 4; p++) {
            float2 u0 = unpack2(acc[p][0]);
            float2 u1 = unpack2(acc[p][1]);
            float2 u2 = unpack2(acc[p][2]);
            float2 u3 = unpack2(acc[p][3]);
            float4 lo = make_float4(u0.x, u1.x, u2.x, u3.x);
            float4 hi = make_float4(u0.y, u1.y, u2.y, u3.y);
            *(float4*)&outp[((size_t)b * C + oc0 + 2*p    ) * LL + lp + lq * 4] = lo;
            *(float4*)&outp[((size_t)b * C + oc0 + 2*p + 1) * LL + lp + lq * 4] = hi;
        }
    }
}

// ---------------------------------------------------------------------------
extern "C" void kernel_launch(void* const* d_in, const int* in_sizes, int n_in,
                              void* d_out, int out_size) {
    const float* x      = (const float*)d_in[0];
    const float* mask   = (const float*)d_in[1];
    const float* w_qkv1 = (const float*)d_in[2];
    const float* b_qkv1 = (const float*)d_in[3];
    const float* w_dw   = (const float*)d_in[4];
    const float* b_dw   = (const float*)d_in[5];
    const float* w_proj = (const float*)d_in[6];
    const float* b_proj = (const float*)d_in[7];
    float* out = (float*)d_out;

    k0_zero<<<1, BATCH * HEADS * CPH * CPH>>>();
    k1_qkv<<<dim3(LL / 256, BATCH), 288>>>(x, w_qkv1, b_qkv1);
    k2_dw<<<(BATCH * C3 * HD) / 8, 256>>>(w_dw, b_dw);
    k3_attn<<<dim3(LL / 4096, BATCH * HEADS), 256>>>();
    k4_soft<<<1, 256>>>(mask, w_proj);
    k5_proj<<<dim3(LL / 256, BATCH), 192>>>(b_proj, out);
}

// round 4
// speedup vs baseline: 1.0156x; 1.0156x over previous
#include <cuda_runtime.h>

#define BATCH 2
#define C     48
#define C3    144
#define DD    32
#define HD    64
#define WD    64
#define LL    (DD*HD*WD)   /* 131072 */
#define HW    (HD*WD)      /* 4096 */
#define HEADS 6
#define CPH   8

// ---- scratch (static device arrays; no runtime allocation) ----
__device__ float g_qkv[(size_t)BATCH * C3 * LL];   // after 1x1x1 conv
__device__ float g_v  [(size_t)BATCH * C  * LL];   // v after depthwise conv
__device__ float g_attn[BATCH * HEADS * CPH * CPH];
__device__ float g_weff[BATCH * C * C];

// ---------------------------------------------------------------------------
// K0: zero the attention accumulator
// ---------------------------------------------------------------------------
__global__ void k0_zero() {
    g_attn[threadIdx.x] = 0.0f;
}

// ---------------------------------------------------------------------------
// K1: qkv = W1[144x48] * x[48xL] + b1    (per batch)
// 288 threads; W loaded once; 4 phases of 64 l (R2 measured-best form)
// ---------------------------------------------------------------------------
__global__ __launch_bounds__(288) void k1_qkv(const float* __restrict__ x,
                                              const float* __restrict__ w1,
                                              const float* __restrict__ b1) {
    __shared__ float  Wt[48][144];   // [ic][oc]
    __shared__ float4 Xs[48][16];    // [ic][l/4]

    const int b  = blockIdx.y;
    const size_t l0 = (size_t)blockIdx.x * 256;
    const int tid = threadIdx.x;

    for (int i = tid; i < C3 * C; i += 288) {
        int oc = i / 48, ic = i % 48;
        Wt[ic][oc] = w1[i];
    }

    const int lq  = tid & 15;        // one float4 (4 l's)
    const int og  = tid >> 4;        // 0..17 -> 8 oc's each
    const int oc0 = og * 8;

#pragma unroll 1
    for (int phase = 0; phase < 4; phase++) {
        const size_t lp = l0 + phase * 64;
        __syncthreads();
        for (int i = tid; i < 48 * 16; i += 288) {
            int ic = i >> 4, j = i & 15;
            Xs[ic][j] = *(const float4*)(x + ((size_t)b * C + ic) * LL + lp + j * 4);
        }
        __syncthreads();

        float4 acc[8];
#pragma unroll
        for (int j = 0; j < 8; j++) acc[j] = make_float4(0.f, 0.f, 0.f, 0.f);

#pragma unroll 4
        for (int ic = 0; ic < 48; ic++) {
            const float4 xv = Xs[ic][lq];
            const float4 wa = *(const float4*)&Wt[ic][oc0];
            const float4 wb = *(const float4*)&Wt[ic][oc0 + 4];
            const float wr[8] = {wa.x, wa.y, wa.z, wa.w, wb.x, wb.y, wb.z, wb.w};
#pragma unroll
            for (int j = 0; j < 8; j++) {
                acc[j].x += wr[j] * xv.x;
                acc[j].y += wr[j] * xv.y;
                acc[j].z += wr[j] * xv.z;
                acc[j].w += wr[j] * xv.w;
            }
        }

#pragma unroll
        for (int j = 0; j < 8; j++) {
            const int oc = oc0 + j;
            const float bb = b1[oc];
            float4 v = acc[j];
            v.x += bb; v.y += bb; v.z += bb; v.w += bb;
            *(float4*)&g_qkv[((size_t)b * C3 + oc) * LL + lp + lq * 4] = v;
        }
    }
}

// ---------------------------------------------------------------------------
// K23: FUSED depthwise(q,k) + channel attention accumulation.
// One 512-thread block per (h, head, b). Warp w computes the rolling-d
// depthwise for channel (q_w or k_{w-8}); each d-slice (16ch x 64w) is staged
// in smem (double-buffered, 1 sync per d) and the same threads accumulate the
// 8x8 q.k^T outer products. q_dw/k_dw never touch DRAM.
// ---------------------------------------------------------------------------
__global__ __launch_bounds__(512) void k23_qk_attn(const float* __restrict__ wdw,
                                                   const float* __restrict__ bdw) {
    const int h    = blockIdx.x;
    const int head = blockIdx.y;
    const int b    = blockIdx.z;
    const int wid  = threadIdx.x >> 5;
    const int lane = threadIdx.x & 31;

    // this warp's channel in the 144-channel qkv tensor
    const int ch = (wid < 8) ? (head * CPH + wid) : (C + head * CPH + (wid - 8));
    const float* base = g_qkv + ((size_t)b * C3 + ch) * LL;

    float w[27];
#pragma unroll
    for (int i = 0; i < 27; i++) w[i] = wdw[ch * 27 + i];
    const float bias = bdw[ch];

    float2 rv[3][3];
    float  rl[3][3], rr[3][3];

    auto loadrow = [&](int d, int hh, int s) {
        const int hr = h + hh - 1;
        float2 v2;
        if (d < 0 || d >= DD || hr < 0 || hr >= HD) v2 = make_float2(0.f, 0.f);
        else v2 = ((const float2*)(base + (size_t)d * HW + hr * WD))[lane];
        float a = __shfl_up_sync(0xffffffffu, v2.y, 1);
        if (lane == 0) a = 0.f;
        float p = __shfl_down_sync(0xffffffffu, v2.x, 1);
        if (lane == 31) p = 0.f;
        rv[s][hh] = v2; rl[s][hh] = a; rr[s][hh] = p;
    };

#pragma unroll
    for (int hh = 0; hh < 3; hh++) {
        rv[0][hh] = make_float2(0.f, 0.f); rl[0][hh] = 0.f; rr[0][hh] = 0.f;
        loadrow(0, hh, 1);
        loadrow(1, hh, 2);
    }

    __shared__ float sQK[2][16][64];
    __shared__ float sA[64];
    if (threadIdx.x < 64) sA[threadIdx.x] = 0.f;

    float acc[8];
#pragma unroll
    for (int j = 0; j < 8; j++) acc[j] = 0.f;

    const int il = threadIdx.x & 63;   // l within the 64-wide row
    const int ir = threadIdx.x >> 6;   // q channel index 0..7

    for (int d = 0; d < DD; d++) {
        // --- depthwise for this warp's channel ---
        float2 o = make_float2(bias, bias);
#pragma unroll
        for (int dd = 0; dd < 3; dd++) {
#pragma unroll
            for (int hh = 0; hh < 3; hh++) {
                const int tb = (dd * 3 + hh) * 3;
                const float w0 = w[tb], w1 = w[tb + 1], w2 = w[tb + 2];
                const float2 v2 = rv[dd][hh];
                o.x += w0 * rl[dd][hh] + w1 * v2.x + w2 * v2.y;
                o.y += w0 * v2.x       + w1 * v2.y + w2 * rr[dd][hh];
            }
        }
        const int buf = d & 1;
        ((float2*)&sQK[buf][wid][0])[lane] = o;
        __syncthreads();

        // --- attention outer-product accumulation ---
        const float qv = sQK[buf][ir][il];
#pragma unroll
        for (int j = 0; j < 8; j++)
            acc[j] += qv * sQK[buf][8 + j][il];

        // --- roll window (writes only touch registers / other buffer) ---
#pragma unroll
        for (int hh = 0; hh < 3; hh++) {
            rv[0][hh] = rv[1][hh]; rl[0][hh] = rl[1][hh]; rr[0][hh] = rr[1][hh];
            rv[1][hh] = rv[2][hh]; rl[1][hh] = rl[2][hh]; rr[1][hh] = rr[2][hh];
            loadrow(d + 2, hh, 2);
        }
    }

    // --- reduce: warp butterfly over l, then smem, then one global atomic ---
#pragma unroll
    for (int j = 0; j < 8; j++) {
        float s = acc[j];
#pragma unroll
        for (int off = 16; off > 0; off >>= 1)
            s += __shfl_xor_sync(0xffffffffu, s, off);
        if (lane == 0) atomicAdd(&sA[ir * 8 + j], s);
    }
    __syncthreads();
    if (threadIdx.x < 64)
        atomicAdd(&g_attn[(b * HEADS + head) * 64 + threadIdx.x], sA[threadIdx.x]);
}

// ---------------------------------------------------------------------------
// K2v: depthwise 3x3x3 for the 48 v channels only -> g_v
// ---------------------------------------------------------------------------
__global__ __launch_bounds__(256) void k2_dw_v(const float* __restrict__ wdw,
                                               const float* __restrict__ bdw) {
    const int gw   = blockIdx.x * 8 + (threadIdx.x >> 5);
    const int lane = threadIdx.x & 31;
    const int h  = gw % HD;
    const int t  = gw / HD;
    const int vc = t % C;
    const int b  = t / C;
    const int ch = 2 * C + vc;

    const float* base  = g_qkv + ((size_t)b * C3 + ch) * LL;
    float*       obase = g_v   + ((size_t)b * C  + vc) * LL;

    float w[27];
#pragma unroll
    for (int i = 0; i < 27; i++) w[i] = wdw[ch * 27 + i];
    const float bias = bdw[ch];

    float2 rv[3][3];
    float  rl[3][3], rr[3][3];

    auto loadrow = [&](int d, int hh, int s) {
        const int hr = h + hh - 1;
        float2 v2;
        if (d < 0 || d >= DD || hr < 0 || hr >= HD) v2 = make_float2(0.f, 0.f);
        else v2 = ((const float2*)(base + (size_t)d * HW + hr * WD))[lane];
        float a = __shfl_up_sync(0xffffffffu, v2.y, 1);
        if (lane == 0) a = 0.f;
        float p = __shfl_down_sync(0xffffffffu, v2.x, 1);
        if (lane == 31) p = 0.f;
        rv[s][hh] = v2; rl[s][hh] = a; rr[s][hh] = p;
    };

#pragma unroll
    for (int hh = 0; hh < 3; hh++) {
        rv[0][hh] = make_float2(0.f, 0.f); rl[0][hh] = 0.f; rr[0][hh] = 0.f;
        loadrow(0, hh, 1);
        loadrow(1, hh, 2);
    }

    for (int d = 0; d < DD; d++) {
        float2 o = make_float2(bias, bias);
#pragma unroll
        for (int dd = 0; dd < 3; dd++) {
#pragma unroll
            for (int hh = 0; hh < 3; hh++) {
                const int tb = (dd * 3 + hh) * 3;
                const float w0 = w[tb], w1 = w[tb + 1], w2 = w[tb + 2];
                const float2 v2 = rv[dd][hh];
                o.x += w0 * rl[dd][hh] + w1 * v2.x + w2 * v2.y;
                o.y += w0 * v2.x       + w1 * v2.y + w2 * rr[dd][hh];
            }
        }
        ((float2*)(obase + (size_t)d * HW + h * WD))[lane] = o;
#pragma unroll
        for (int hh = 0; hh < 3; hh++) {
            rv[0][hh] = rv[1][hh]; rl[0][hh] = rl[1][hh]; rr[0][hh] = rr[1][hh];
            rv[1][hh] = rv[2][hh]; rl[1][hh] = rl[2][hh]; rr[1][hh] = rr[2][hh];
            loadrow(d + 2, hh, 2);
        }
    }
}

// ---------------------------------------------------------------------------
// K4: softmax(scale*attn + mask) then fold proj into a per-batch 48x48 Weff
// ---------------------------------------------------------------------------
__global__ __launch_bounds__(256) void k4_soft(const float* __restrict__ mask,
                                               const float* __restrict__ wproj) {
    const int tid = threadIdx.x;
    __shared__ float A[BATCH * HEADS * CPH * CPH];
    const float scale = 0.40824829046386307f;  // 6^-0.5

    if (tid < BATCH * HEADS * CPH) {  // 96 rows
        const int b = tid / (HEADS * CPH);
        const int r = tid % (HEADS * CPH);
        const int hd = r / CPH, c = r % CPH;
        float v[8];
        float mx = -1e30f;
#pragma unroll
        for (int j = 0; j < 8; j++) {
            v[j] = g_attn[((b * HEADS + hd) * CPH + c) * CPH + j] * scale
                 + mask[(b * CPH + c) * CPH + j];
            mx = fmaxf(mx, v[j]);
        }
        float s = 0.f;
#pragma unroll
        for (int j = 0; j < 8; j++) { v[j] = expf(v[j] - mx); s += v[j]; }
        const float inv = 1.f / s;
#pragma unroll
        for (int j = 0; j < 8; j++)
            A[((b * HEADS + hd) * CPH + c) * CPH + j] = v[j] * inv;
    }
    __syncthreads();

    for (int i = tid; i < BATCH * C * C; i += 256) {
        const int b = i / (C * C);
        const int r = i % (C * C);
        const int oc = r / C, c2 = r % C;
        const int hd = c2 / CPH, j = c2 % CPH;
        float s = 0.f;
#pragma unroll
        for (int ii = 0; ii < 8; ii++)
            s += wproj[oc * C + hd * CPH + ii]
               * A[((b * HEADS + hd) * CPH + ii) * CPH + j];
        g_weff[i] = s;
    }
}

// ---------------------------------------------------------------------------
// K5: out[48,L] = Weff[b][48x48] * v_dw[48,L] + b_proj
// 192 threads; W loaded once; 2 phases of 128 l (R2 measured-best form)
// ---------------------------------------------------------------------------
__global__ __launch_bounds__(192) void k5_proj(const float* __restrict__ bproj,
                                               float* __restrict__ outp) {
    __shared__ float  Wt[48][48];    // [c2][oc]
    __shared__ float4 Vs[48][32];    // [c2][l/4]

    const int b  = blockIdx.y;
    const size_t l0 = (size_t)blockIdx.x * 256;
    const int tid = threadIdx.x;

    for (int i = tid; i < C * C; i += 192) {
        int oc = i / 48, c2 = i % 48;
        Wt[c2][oc] = g_weff[b * C * C + i];
    }

    const int lq  = tid & 31;   // one float4 (4 l's)
    const int og  = tid >> 5;   // 0..5 -> 8 oc's each
    const int oc0 = og * 8;

#pragma unroll 1
    for (int phase = 0; phase < 2; phase++) {
        const size_t lp = l0 + phase * 128;
        __syncthreads();
        for (int i = tid; i < 48 * 32; i += 192) {
            int ic = i >> 5, j = i & 31;
            Vs[ic][j] = *(const float4*)(g_v + ((size_t)b * C + ic) * LL + lp + j * 4);
        }
        __syncthreads();

        float4 acc[8];
#pragma unroll
        for (int j = 0; j < 8; j++) acc[j] = make_float4(0.f, 0.f, 0.f, 0.f);

#pragma unroll 4
        for (int c2 = 0; c2 < 48; c2++) {
            const float4 xv = Vs[c2][lq];
            const float4 wa = *(const float4*)&Wt[c2][oc0];
            const float4 wb = *(const float4*)&Wt[c2][oc0 + 4];
            const float wr[8] = {wa.x, wa.y, wa.z, wa.w, wb.x, wb.y, wb.z, wb.w};
#pragma unroll
            for (int j = 0; j < 8; j++) {
                acc[j].x += wr[j] * xv.x;
                acc[j].y += wr[j] * xv.y;
                acc[j].z += wr[j] * xv.z;
                acc[j].w += wr[j] * xv.w;
            }
        }

#pragma unroll
        for (int j = 0; j < 8; j++) {
            const int oc = oc0 + j;
            const float bb = bproj[oc];
            float4 v = acc[j];
            v.x += bb; v.y += bb; v.z += bb; v.w += bb;
            *(float4*)&outp[((size_t)b * C + oc) * LL + lp + lq * 4] = v;
        }
    }
}

// ---------------------------------------------------------------------------
extern "C" void kernel_launch(void* const* d_in, const int* in_sizes, int n_in,
                              void* d_out, int out_size) {
    const float* x      = (const float*)d_in[0];
    const float* mask   = (const float*)d_in[1];
    const float* w_qkv1 = (const float*)d_in[2];
    const float* b_qkv1 = (const float*)d_in[3];
    const float* w_dw   = (const float*)d_in[4];
    const float* b_dw   = (const float*)d_in[5];
    const float* w_proj = (const float*)d_in[6];
    const float* b_proj = (const float*)d_in[7];
    float* out = (float*)d_out;

    k0_zero<<<1, BATCH * HEADS * CPH * CPH>>>();
    k1_qkv<<<dim3(LL / 256, BATCH), 288>>>(x, w_qkv1, b_qkv1);
    k23_qk_attn<<<dim3(HD, HEADS, BATCH), 512>>>(w_dw, b_dw);
    k2_dw_v<<<(BATCH * C * HD) / 8, 256>>>(w_dw, b_dw);
    k4_soft<<<1, 256>>>(mask, w_proj);
    k5_proj<<<dim3(LL / 256, BATCH), 192>>>(b_proj, out);
}

// round 5
// speedup vs baseline: 1.1337x; 1.1163x over previous
#include <cuda_runtime.h>

#define BATCH 2
#define C     48
#define C3    144
#define DD    32
#define HD    64
#define WD    64
#define LL    (DD*HD*WD)   /* 131072 */
#define HW    (HD*WD)      /* 4096 */
#define HEADS 6
#define CPH   8

// ---- scratch (static device arrays; no runtime allocation) ----
__device__ float g_qkv[(size_t)BATCH * C3 * LL];   // after 1x1x1 conv
__device__ float g_dw [(size_t)BATCH * C3 * LL];   // after depthwise conv
__device__ float g_attn[BATCH * HEADS * CPH * CPH];
__device__ float g_weff[BATCH * C * C];

// ---------------------------------------------------------------------------
// K0: zero the attention accumulator
// ---------------------------------------------------------------------------
__global__ void k0_zero() {
    g_attn[threadIdx.x] = 0.0f;
}

// ---------------------------------------------------------------------------
// K1: qkv = W1[144x48] * x[48xL] + b1    (per batch)
// 288 threads; W loaded once; 4 phases of 64 l (R2 measured-best form)
// ---------------------------------------------------------------------------
__global__ __launch_bounds__(288) void k1_qkv(const float* __restrict__ x,
                                              const float* __restrict__ w1,
                                              const float* __restrict__ b1) {
    __shared__ float  Wt[48][144];   // [ic][oc]
    __shared__ float4 Xs[48][16];    // [ic][l/4]

    const int b  = blockIdx.y;
    const size_t l0 = (size_t)blockIdx.x * 256;
    const int tid = threadIdx.x;

    for (int i = tid; i < C3 * C; i += 288) {
        int oc = i / 48, ic = i % 48;
        Wt[ic][oc] = w1[i];
    }

    const int lq  = tid & 15;        // one float4 (4 l's)
    const int og  = tid >> 4;        // 0..17 -> 8 oc's each
    const int oc0 = og * 8;

#pragma unroll 1
    for (int phase = 0; phase < 4; phase++) {
        const size_t lp = l0 + phase * 64;
        __syncthreads();
        for (int i = tid; i < 48 * 16; i += 288) {
            int ic = i >> 4, j = i & 15;
            Xs[ic][j] = *(const float4*)(x + ((size_t)b * C + ic) * LL + lp + j * 4);
        }
        __syncthreads();

        float4 acc[8];
#pragma unroll
        for (int j = 0; j < 8; j++) acc[j] = make_float4(0.f, 0.f, 0.f, 0.f);

#pragma unroll 4
        for (int ic = 0; ic < 48; ic++) {
            const float4 xv = Xs[ic][lq];
            const float4 wa = *(const float4*)&Wt[ic][oc0];
            const float4 wb = *(const float4*)&Wt[ic][oc0 + 4];
            const float wr[8] = {wa.x, wa.y, wa.z, wa.w, wb.x, wb.y, wb.z, wb.w};
#pragma unroll
            for (int j = 0; j < 8; j++) {
                acc[j].x += wr[j] * xv.x;
                acc[j].y += wr[j] * xv.y;
                acc[j].z += wr[j] * xv.z;
                acc[j].w += wr[j] * xv.w;
            }
        }

#pragma unroll
        for (int j = 0; j < 8; j++) {
            const int oc = oc0 + j;
            const float bb = b1[oc];
            float4 v = acc[j];
            v.x += bb; v.y += bb; v.z += bb; v.w += bb;
            *(float4*)&g_qkv[((size_t)b * C3 + oc) * LL + lp + lq * 4] = v;
        }
    }
}

// ---------------------------------------------------------------------------
// K2: depthwise 3x3x3 SAME conv over all 144 channels.
// One warp per (b, ch, h). launch_bounds(256,3) caps regs -> 24 warps/SM
// (was 16): this kernel is occupancy/latency-bound per R4 profile.
// ---------------------------------------------------------------------------
__global__ __launch_bounds__(256, 3) void k2_dw(const float* __restrict__ wdw,
                                                const float* __restrict__ bdw) {
    const int gw   = blockIdx.x * 8 + (threadIdx.x >> 5);
    const int lane = threadIdx.x & 31;
    const int h  = gw % HD;
    const int t  = gw / HD;
    const int ch = t % C3;
    const int b  = t / C3;

    const float* base  = g_qkv + ((size_t)b * C3 + ch) * LL;
    float*       obase = g_dw  + ((size_t)b * C3 + ch) * LL;

    float w[27];
#pragma unroll
    for (int i = 0; i < 27; i++) w[i] = wdw[ch * 27 + i];
    const float bias = bdw[ch];

    float2 rv[3][3];
    float  rl[3][3], rr[3][3];

    auto loadrow = [&](int d, int hh, int s) {
        const int hr = h + hh - 1;
        float2 v2;
        if (d < 0 || d >= DD || hr < 0 || hr >= HD) v2 = make_float2(0.f, 0.f);
        else v2 = ((const float2*)(base + (size_t)d * HW + hr * WD))[lane];
        float a = __shfl_up_sync(0xffffffffu, v2.y, 1);
        if (lane == 0) a = 0.f;
        float p = __shfl_down_sync(0xffffffffu, v2.x, 1);
        if (lane == 31) p = 0.f;
        rv[s][hh] = v2; rl[s][hh] = a; rr[s][hh] = p;
    };

#pragma unroll
    for (int hh = 0; hh < 3; hh++) {
        rv[0][hh] = make_float2(0.f, 0.f); rl[0][hh] = 0.f; rr[0][hh] = 0.f;
        loadrow(0, hh, 1);
        loadrow(1, hh, 2);
    }

    for (int d = 0; d < DD; d++) {
        float2 o = make_float2(bias, bias);
#pragma unroll
        for (int dd = 0; dd < 3; dd++) {
#pragma unroll
            for (int hh = 0; hh < 3; hh++) {
                const int tb = (dd * 3 + hh) * 3;
                const float w0 = w[tb], w1 = w[tb + 1], w2 = w[tb + 2];
                const float2 v2 = rv[dd][hh];
                o.x += w0 * rl[dd][hh] + w1 * v2.x + w2 * v2.y;
                o.y += w0 * v2.x       + w1 * v2.y + w2 * rr[dd][hh];
            }
        }
        ((float2*)(obase + (size_t)d * HW + h * WD))[lane] = o;
#pragma unroll
        for (int hh = 0; hh < 3; hh++) {
            rv[0][hh] = rv[1][hh]; rl[0][hh] = rl[1][hh]; rr[0][hh] = rr[1][hh];
            rv[1][hh] = rv[2][hh]; rl[1][hh] = rl[2][hh]; rr[1][hh] = rr[2][hh];
            loadrow(d + 2, hh, 2);
        }
    }
}

// ---------------------------------------------------------------------------
// K3: attn[b,h,c,d] += sum_l q[b,h,c,l] * k[b,h,d,l]
// R1 measured-best form (scalar loads, compiler unroll), chunk 2048 -> grid 768
// ---------------------------------------------------------------------------
__global__ __launch_bounds__(256) void k3_attn() {
    const int chunk = blockIdx.x;
    const int bh = blockIdx.y;
    const int b = bh / HEADS, hd = bh % HEADS;

    const float* qb = g_dw + ((size_t)b * C3 + hd * CPH) * LL + (size_t)chunk * 2048;
    const float* kb = qb + (size_t)C * LL;

    float acc[64];
#pragma unroll
    for (int i = 0; i < 64; i++) acc[i] = 0.f;

    for (int it = 0; it < 8; it++) {
        const int l = it * 256 + threadIdx.x;
        float q[8], k[8];
#pragma unroll
        for (int i = 0; i < 8; i++) {
            q[i] = qb[(size_t)i * LL + l];
            k[i] = kb[(size_t)i * LL + l];
        }
#pragma unroll
        for (int i = 0; i < 8; i++)
#pragma unroll
            for (int j = 0; j < 8; j++)
                acc[i * 8 + j] += q[i] * k[j];
    }

    __shared__ float red[64];
    if (threadIdx.x < 64) red[threadIdx.x] = 0.f;
    __syncthreads();
    const int lane = threadIdx.x & 31;
#pragma unroll
    for (int v = 0; v < 64; v++) {
        float s = acc[v];
#pragma unroll
        for (int off = 16; off > 0; off >>= 1)
            s += __shfl_xor_sync(0xffffffffu, s, off);
        if (lane == 0) atomicAdd(&red[v], s);
    }
    __syncthreads();
    if (threadIdx.x < 64)
        atomicAdd(&g_attn[bh * 64 + threadIdx.x], red[threadIdx.x]);
}

// ---------------------------------------------------------------------------
// K4: softmax(scale*attn + mask) then fold proj into a per-batch 48x48 Weff
// ---------------------------------------------------------------------------
__global__ __launch_bounds__(256) void k4_soft(const float* __restrict__ mask,
                                               const float* __restrict__ wproj) {
    const int tid = threadIdx.x;
    __shared__ float A[BATCH * HEADS * CPH * CPH];
    const float scale = 0.40824829046386307f;  // 6^-0.5

    if (tid < BATCH * HEADS * CPH) {  // 96 rows
        const int b = tid / (HEADS * CPH);
        const int r = tid % (HEADS * CPH);
        const int hd = r / CPH, c = r % CPH;
        float v[8];
        float mx = -1e30f;
#pragma unroll
        for (int j = 0; j < 8; j++) {
            v[j] = g_attn[((b * HEADS + hd) * CPH + c) * CPH + j] * scale
                 + mask[(b * CPH + c) * CPH + j];
            mx = fmaxf(mx, v[j]);
        }
        float s = 0.f;
#pragma unroll
        for (int j = 0; j < 8; j++) { v[j] = expf(v[j] - mx); s += v[j]; }
        const float inv = 1.f / s;
#pragma unroll
        for (int j = 0; j < 8; j++)
            A[((b * HEADS + hd) * CPH + c) * CPH + j] = v[j] * inv;
    }
    __syncthreads();

    for (int i = tid; i < BATCH * C * C; i += 256) {
        const int b = i / (C * C);
        const int r = i % (C * C);
        const int oc = r / C, c2 = r % C;
        const int hd = c2 / CPH, j = c2 % CPH;
        float s = 0.f;
#pragma unroll
        for (int ii = 0; ii < 8; ii++)
            s += wproj[oc * C + hd * CPH + ii]
               * A[((b * HEADS + hd) * CPH + ii) * CPH + j];
        g_weff[i] = s;
    }
}

// ---------------------------------------------------------------------------
// K5: out[48,L] = Weff[b][48x48] * v_dw[48,L] + b_proj
// 192 threads; W loaded once; 2 phases of 128 l (R2 measured-best form)
// ---------------------------------------------------------------------------
__global__ __launch_bounds__(192) void k5_proj(const float* __restrict__ bproj,
                                               float* __restrict__ outp) {
    __shared__ float  Wt[48][48];    // [c2][oc]
    __shared__ float4 Vs[48][32];    // [c2][l/4]

    const int b  = blockIdx.y;
    const size_t l0 = (size_t)blockIdx.x * 256;
    const int tid = threadIdx.x;

    for (int i = tid; i < C * C; i += 192) {
        int oc = i / 48, c2 = i % 48;
        Wt[c2][oc] = g_weff[b * C * C + i];
    }

    const int lq  = tid & 31;   // one float4 (4 l's)
    const int og  = tid >> 5;   // 0..5 -> 8 oc's each
    const int oc0 = og * 8;

#pragma unroll 1
    for (int phase = 0; phase < 2; phase++) {
        const size_t lp = l0 + phase * 128;
        __syncthreads();
        for (int i = tid; i < 48 * 32; i += 192) {
            int ic = i >> 5, j = i & 31;
            Vs[ic][j] = *(const float4*)(g_dw + ((size_t)b * C3 + 2 * C + ic) * LL + lp + j * 4);
        }
        __syncthreads();

        float4 acc[8];
#pragma unroll
        for (int j = 0; j < 8; j++) acc[j] = make_float4(0.f, 0.f, 0.f, 0.f);

#pragma unroll 4
        for (int c2 = 0; c2 < 48; c2++) {
            const float4 xv = Vs[c2][lq];
            const float4 wa = *(const float4*)&Wt[c2][oc0];
            const float4 wb = *(const float4*)&Wt[c2][oc0 + 4];
            const float wr[8] = {wa.x, wa.y, wa.z, wa.w, wb.x, wb.y, wb.z, wb.w};
#pragma unroll
            for (int j = 0; j < 8; j++) {
                acc[j].x += wr[j] * xv.x;
                acc[j].y += wr[j] * xv.y;
                acc[j].z += wr[j] * xv.z;
                acc[j].w += wr[j] * xv.w;
            }
        }

#pragma unroll
        for (int j = 0; j < 8; j++) {
            const int oc = oc0 + j;
            const float bb = bproj[oc];
            float4 v = acc[j];
            v.x += bb; v.y += bb; v.z += bb; v.w += bb;
            *(float4*)&outp[((size_t)b * C + oc) * LL + lp + lq * 4] = v;
        }
    }
}

// ---------------------------------------------------------------------------
extern "C" void kernel_launch(void* const* d_in, const int* in_sizes, int n_in,
                              void* d_out, int out_size) {
    const float* x      = (const float*)d_in[0];
    const float* mask   = (const float*)d_in[1];
    const float* w_qkv1 = (const float*)d_in[2];
    const float* b_qkv1 = (const float*)d_in[3];
    const float* w_dw   = (const float*)d_in[4];
    const float* b_dw   = (const float*)d_in[5];
    const float* w_proj = (const float*)d_in[6];
    const float* b_proj = (const float*)d_in[7];
    float* out = (float*)d_out;

    k0_zero<<<1, BATCH * HEADS * CPH * CPH>>>();
    k1_qkv<<<dim3(LL / 256, BATCH), 288>>>(x, w_qkv1, b_qkv1);
    k2_dw<<<(BATCH * C3 * HD) / 8, 256>>>(w_dw, b_dw);
    k3_attn<<<dim3(LL / 2048, BATCH * HEADS), 256>>>();
    k4_soft<<<1, 256>>>(mask, w_proj);
    k5_proj<<<dim3(LL / 256, BATCH), 192>>>(b_proj, out);
}